// round 6
// baseline (speedup 1.0000x reference)
#include <cuda_runtime.h>

// PMLoss fused single-kernel, heavy-first block remap.
// B=128 ROIs, C=22 classes, P=1024 points. grid=512, TPB=128, 2 points/thread.
// Every block computes the sym bitmap (identical result), then maps blockIdx
// so symmetric (heavy) work items get consecutive block ids 0..4*nheavy-1 ->
// classic placement puts <=1 heavy block per SM. Deterministic.

#define NB 128
#define NC 22
#define NP 1024
#define CH 4
#define PPB (NP / CH)     // 256
#define TPB 128
#define GRID (NB * CH)    // 512

__device__ float g_partials[GRID];
__device__ unsigned int g_ticket = 0;

__device__ __forceinline__ void quat2mat(float w, float x, float y, float z,
                                         float* R) {
    R[0] = 1.f - 2.f * (y * y + z * z);
    R[1] = 2.f * (x * y - w * z);
    R[2] = 2.f * (x * z + w * y);
    R[3] = 2.f * (x * y + w * z);
    R[4] = 1.f - 2.f * (x * x + z * z);
    R[5] = 2.f * (y * z - w * x);
    R[6] = 2.f * (x * z - w * y);
    R[7] = 2.f * (y * z + w * x);
    R[8] = 1.f - 2.f * (x * x + y * y);
}

__device__ __forceinline__ unsigned long long ffma2(unsigned long long a,
                                                    unsigned long long b,
                                                    unsigned long long c) {
    unsigned long long d;
    asm("fma.rn.f32x2 %0, %1, %2, %3;" : "=l"(d) : "l"(a), "l"(b), "l"(c));
    return d;
}
__device__ __forceinline__ unsigned long long pack2(float a, float b) {
    unsigned long long r;
    asm("mov.b64 %0, {%1, %2};" : "=l"(r) : "f"(a), "f"(b));
    return r;
}
__device__ __forceinline__ float2 unpack2(unsigned long long v) {
    float2 r;
    asm("mov.b64 {%0, %1}, %2;" : "=f"(r.x), "=f"(r.y) : "l"(v));
    return r;
}

__device__ __forceinline__ float block_reduce_128(float d, float* s_red,
                                                  int tid) {
#pragma unroll
    for (int o = 16; o > 0; o >>= 1) d += __shfl_down_sync(0xffffffffu, d, o);
    if ((tid & 31) == 0) s_red[tid >> 5] = d;
    __syncthreads();
    if (tid < 4) {
        d = s_red[tid];
        d += __shfl_down_sync(0xfu, d, 2);
        d += __shfl_down_sync(0xfu, d, 1);
    }
    return d;
}

__global__ __launch_bounds__(TPB) void pm_fused_kernel(
    const float* __restrict__ pred, const float* __restrict__ tgt,
    const float* __restrict__ wt, const float* __restrict__ pts,
    const float* __restrict__ sym, float* __restrict__ out) {
    __shared__ float sA[NP * 2];   // pair-packed: {x2j,x2j+1,y2j,y2j+1}
    __shared__ float sB[NP * 2];   // pair-packed: {z2j,z2j+1,w2j,w2j+1}
    __shared__ float sR[18];       // Rp 0..8, Rt 9..17
    __shared__ float s_red[4];
    __shared__ unsigned char s_clsArr[NB];
    __shared__ unsigned s_mask[4];

    const int tid = threadIdx.x;
    const int bid = blockIdx.x;
    const int lane = tid & 31;
    const int wid = tid >> 5;

    // ---- per-block (redundant, identical) sym-bitmap computation ----
    // Thread t owns ROI t: find its class and symmetry flag.
    {
        int cls_t = 0;
        const float* wrow = wt + tid * 4 * NC;
#pragma unroll
        for (int c = 1; c < NC; c++) {
            if (wrow[4 * c] > 0.5f) { cls_t = c; break; }
        }
        s_clsArr[tid] = (unsigned char)cls_t;
        bool sym_t = (sym[cls_t] > 0.0f);
        unsigned bal = __ballot_sync(0xffffffffu, sym_t);
        if (lane == 0) s_mask[wid] = bal;
    }
    __syncthreads();

    unsigned mm0 = s_mask[0], mm1 = s_mask[1], mm2 = s_mask[2], mm3 = s_mask[3];
    const int nheavy =
        __popc(mm0) + __popc(mm1) + __popc(mm2) + __popc(mm3);

    // ---- map bid -> (ROI b, chunk, heavy?) : heavy items first ----
    int b, chunk;
    bool heavy;
    {
        unsigned w0, w1, w2, w3;
        int k;
        if (bid < 4 * nheavy) {
            heavy = true;
            k = bid >> 2;
            chunk = bid & 3;
            w0 = mm0; w1 = mm1; w2 = mm2; w3 = mm3;
        } else {
            heavy = false;
            int r = bid - 4 * nheavy;
            k = r >> 2;
            chunk = r & 3;
            w0 = ~mm0; w1 = ~mm1; w2 = ~mm2; w3 = ~mm3;
        }
        // find k-th set bit across w0..w3
        int base = 0;
        unsigned x = w0;
        int p = __popc(w0);
        if (k >= p) { k -= p; base = 32; x = w1; p = __popc(w1); }
        if (k >= p) { k -= p; base += 32; x = w2; p = __popc(w2); }
        if (k >= p) { k -= p; base += 32; x = w3; }
        for (int i = 0; i < k; i++) x &= x - 1;
        b = base + __ffs(x) - 1;
    }
    const int cls = s_clsArr[b];

    // ---- quats -> rotation matrices for ROI b (lane work) ----
    if (tid == 0) {
        const float* qp = pred + b * 4 * NC + cls * 4;
        float qw = qp[0], qx = qp[1], qy = qp[2], qz = qp[3];
        float inv = rsqrtf(qw * qw + qx * qx + qy * qy + qz * qz);
        quat2mat(qw * inv, qx * inv, qy * inv, qz * inv, sR);
        const float* qt = tgt + b * 4 * NC + cls * 4;   // unit-norm already
        quat2mat(qt[0], qt[1], qt[2], qt[3], sR + 9);
    }
    __syncthreads();

    const float* __restrict__ mp = pts + (size_t)cls * NP * 3;
    const int p0 = chunk * PPB + tid;   // this thread's two points
    const int p1 = p0 + TPB;
    float d;

    if (!heavy) {
        // Pointwise: |(Rp - Rt) x|^2 for both points.
        float D0 = sR[0] - sR[9],  D1 = sR[1] - sR[10], D2 = sR[2] - sR[11];
        float D3 = sR[3] - sR[12], D4 = sR[4] - sR[13], D5 = sR[5] - sR[14];
        float D6 = sR[6] - sR[15], D7 = sR[7] - sR[16], D8 = sR[8] - sR[17];
        d = 0.f;
#pragma unroll
        for (int pi = 0; pi < 2; pi++) {
            int p = pi ? p1 : p0;
            float x = mp[3 * p + 0], y = mp[3 * p + 1], z = mp[3 * p + 2];
            float dx = D0 * x + D1 * y + D2 * z;
            float dy = D3 * x + D4 * y + D5 * z;
            float dz = D6 * x + D7 * y + D8 * z;
            d += dx * dx + dy * dy + dz * dz;
        }
    } else {
        // Fill target-rotated points (pair-packed) into shared.
        {
            float T0 = sR[9],  T1 = sR[10], T2 = sR[11];
            float T3 = sR[12], T4 = sR[13], T5 = sR[14];
            float T6 = sR[15], T7 = sR[16], T8 = sR[17];
#pragma unroll
            for (int q = tid; q < NP; q += TPB) {
                float x = mp[3 * q + 0], y = mp[3 * q + 1], z = mp[3 * q + 2];
                float tx = T0 * x + T1 * y + T2 * z;
                float ty = T3 * x + T4 * y + T5 * z;
                float tz = T6 * x + T7 * y + T8 * z;
                int j = q >> 1, h = q & 1;
                sA[4 * j + h] = tx;
                sA[4 * j + 2 + h] = ty;
                sB[4 * j + h] = tz;
                sB[4 * j + 2 + h] = tx * tx + ty * ty + tz * tz;
            }
        }
        float px0, py0, pz0, px1, py1, pz1;
        {
            float P0 = sR[0], P1 = sR[1], P2 = sR[2];
            float P3 = sR[3], P4 = sR[4], P5 = sR[5];
            float P6 = sR[6], P7 = sR[7], P8 = sR[8];
            float x = mp[3 * p0 + 0], y = mp[3 * p0 + 1], z = mp[3 * p0 + 2];
            px0 = P0 * x + P1 * y + P2 * z;
            py0 = P3 * x + P4 * y + P5 * z;
            pz0 = P6 * x + P7 * y + P8 * z;
            x = mp[3 * p1 + 0]; y = mp[3 * p1 + 1]; z = mp[3 * p1 + 2];
            px1 = P0 * x + P1 * y + P2 * z;
            py1 = P3 * x + P4 * y + P5 * z;
            pz1 = P6 * x + P7 * y + P8 * z;
        }
        __syncthreads();

        const unsigned long long ax0 = pack2(-2.f * px0, -2.f * px0);
        const unsigned long long ay0 = pack2(-2.f * py0, -2.f * py0);
        const unsigned long long az0 = pack2(-2.f * pz0, -2.f * pz0);
        const unsigned long long ax1 = pack2(-2.f * px1, -2.f * px1);
        const unsigned long long ay1 = pack2(-2.f * py1, -2.f * py1);
        const unsigned long long az1 = pack2(-2.f * pz1, -2.f * pz1);
        const ulonglong2* __restrict__ pA = (const ulonglong2*)sA;
        const ulonglong2* __restrict__ pB = (const ulonglong2*)sB;

        const float INF = 3.402823466e38f;
        float m0a = INF, m0b = INF, m0c = INF, m0d = INF;
        float m1a = INF, m1b = INF, m1c = INF, m1d = INF;
#pragma unroll 4
        for (int j = 0; j < NP / 4; j++) {
            ulonglong2 A0 = pA[2 * j];
            ulonglong2 B0 = pB[2 * j];
            ulonglong2 A1 = pA[2 * j + 1];
            ulonglong2 B1 = pB[2 * j + 1];

            unsigned long long v;
            float2 vf;
            v = ffma2(ax0, A0.x, B0.y);
            v = ffma2(ay0, A0.y, v);
            v = ffma2(az0, B0.x, v);
            vf = unpack2(v);
            m0a = fminf(m0a, vf.x);
            m0b = fminf(m0b, vf.y);
            v = ffma2(ax1, A0.x, B0.y);
            v = ffma2(ay1, A0.y, v);
            v = ffma2(az1, B0.x, v);
            vf = unpack2(v);
            m1a = fminf(m1a, vf.x);
            m1b = fminf(m1b, vf.y);
            v = ffma2(ax0, A1.x, B1.y);
            v = ffma2(ay0, A1.y, v);
            v = ffma2(az0, B1.x, v);
            vf = unpack2(v);
            m0c = fminf(m0c, vf.x);
            m0d = fminf(m0d, vf.y);
            v = ffma2(ax1, A1.x, B1.y);
            v = ffma2(ay1, A1.y, v);
            v = ffma2(az1, B1.x, v);
            vf = unpack2(v);
            m1c = fminf(m1c, vf.x);
            m1d = fminf(m1d, vf.y);
        }
        float d0 = fminf(fminf(m0a, m0b), fminf(m0c, m0d)) +
                   (px0 * px0 + py0 * py0 + pz0 * pz0);
        float d1 = fminf(fminf(m1a, m1b), fminf(m1c, m1d)) +
                   (px1 * px1 + py1 * py1 + pz1 * pz1);
        d = d0 + d1;
    }

    // ---- block partial ----
    float tot = block_reduce_128(d, s_red, tid);
    __shared__ int s_last;
    if (tid == 0) {
        g_partials[bid] = tot;
        __threadfence();
        unsigned t = atomicAdd(&g_ticket, 1u);
        s_last = (t == GRID - 1) ? 1 : 0;
    }
    __syncthreads();

    // ---- last block: deterministic fixed-order global reduction ----
    if (s_last) {
        __threadfence();   // acquire
        float v = 0.f;
#pragma unroll
        for (int i = 0; i < GRID / TPB; i++)
            v += __ldcg(&g_partials[tid + i * TPB]);
        float total = block_reduce_128(v, s_red, tid);
        if (tid == 0) {
            out[0] = total * (1.0f / (2.0f * NB * NP));
            g_ticket = 0;   // reset for next graph replay
        }
    }
}

extern "C" void kernel_launch(void* const* d_in, const int* in_sizes, int n_in,
                              void* d_out, int out_size) {
    const float* pred = (const float*)d_in[0];
    const float* tgt  = (const float*)d_in[1];
    const float* wt   = (const float*)d_in[2];
    const float* pts  = (const float*)d_in[3];
    const float* sym  = (const float*)d_in[4];
    float* out = (float*)d_out;

    pm_fused_kernel<<<GRID, TPB>>>(pred, tgt, wt, pts, sym, out);
}

// round 7
// speedup vs baseline: 1.0715x; 1.0715x over previous
#include <cuda_runtime.h>

// PMLoss fused single-kernel. B=128 ROIs, C=22 classes, P=1024 points.
// grid=512: b = blk/4, chunk = blk%4, 2 points/thread (TPB=128).
// Heavy (symmetric) inner loop is software-pipelined: 8 q's per iteration
// with explicit next-iteration LDS prefetch into a second register buffer.
// __launch_bounds__(128,1) frees the register cap so the buffers stay in regs.

#define NB 128
#define NC 22
#define NP 1024
#define CH 4
#define PPB (NP / CH)     // 256
#define TPB 128
#define GRID (NB * CH)    // 512

__device__ float g_partials[GRID];
__device__ unsigned int g_ticket = 0;

__device__ __forceinline__ void quat2mat(float w, float x, float y, float z,
                                         float* R) {
    R[0] = 1.f - 2.f * (y * y + z * z);
    R[1] = 2.f * (x * y - w * z);
    R[2] = 2.f * (x * z + w * y);
    R[3] = 2.f * (x * y + w * z);
    R[4] = 1.f - 2.f * (x * x + z * z);
    R[5] = 2.f * (y * z - w * x);
    R[6] = 2.f * (x * z - w * y);
    R[7] = 2.f * (y * z + w * x);
    R[8] = 1.f - 2.f * (x * x + y * y);
}

__device__ __forceinline__ unsigned long long ffma2(unsigned long long a,
                                                    unsigned long long b,
                                                    unsigned long long c) {
    unsigned long long d;
    asm("fma.rn.f32x2 %0, %1, %2, %3;" : "=l"(d) : "l"(a), "l"(b), "l"(c));
    return d;
}
__device__ __forceinline__ unsigned long long pack2(float a, float b) {
    unsigned long long r;
    asm("mov.b64 %0, {%1, %2};" : "=l"(r) : "f"(a), "f"(b));
    return r;
}
__device__ __forceinline__ float2 unpack2(unsigned long long v) {
    float2 r;
    asm("mov.b64 {%0, %1}, %2;" : "=f"(r.x), "=f"(r.y) : "l"(v));
    return r;
}

__device__ __forceinline__ float block_reduce_128(float d, float* s_red,
                                                  int tid) {
#pragma unroll
    for (int o = 16; o > 0; o >>= 1) d += __shfl_down_sync(0xffffffffu, d, o);
    if ((tid & 31) == 0) s_red[tid >> 5] = d;
    __syncthreads();
    if (tid < 4) {
        d = s_red[tid];
        d += __shfl_down_sync(0xfu, d, 2);
        d += __shfl_down_sync(0xfu, d, 1);
    }
    return d;
}

__global__ __launch_bounds__(TPB, 1) void pm_fused_kernel(
    const float* __restrict__ pred, const float* __restrict__ tgt,
    const float* __restrict__ wt, const float* __restrict__ pts,
    const float* __restrict__ sym, float* __restrict__ out) {
    // Pair-packed target points: sA pair j = {x2j, x2j+1, y2j, y2j+1}
    //                            sB pair j = {z2j, z2j+1, w2j, w2j+1}
    __shared__ float sA[NP * 2];
    __shared__ float sB[NP * 2];
    __shared__ float sR[18];          // Rp 0..8, Rt 9..17
    __shared__ int s_cls, s_issym;
    __shared__ float s_red[4];

    const int b = blockIdx.x / CH;
    const int chunk = blockIdx.x % CH;
    const int tid = threadIdx.x;

    // ---- setup: parallel class find (warp 0), quat->mat (lane 0) ----
    if (tid < 32) {
        bool hit = (tid >= 1) && (tid < NC) &&
                   (wt[b * 4 * NC + 4 * tid] > 0.5f);
        unsigned m = __ballot_sync(0xffffffffu, hit);
        if (tid == 0) {
            int cls = m ? (__ffs(m) - 1) : 0;
            s_cls = cls;
            s_issym = (sym[cls] > 0.0f) ? 1 : 0;
            const float* qp = pred + b * 4 * NC + cls * 4;
            float qw = qp[0], qx = qp[1], qy = qp[2], qz = qp[3];
            float inv = rsqrtf(qw * qw + qx * qx + qy * qy + qz * qz);
            quat2mat(qw * inv, qx * inv, qy * inv, qz * inv, sR);
            const float* qt = tgt + b * 4 * NC + cls * 4;  // unit-norm
            quat2mat(qt[0], qt[1], qt[2], qt[3], sR + 9);
        }
    }
    __syncthreads();

    const int cls = s_cls;
    const float* __restrict__ mp = pts + (size_t)cls * NP * 3;
    const int p0 = chunk * PPB + tid;        // this thread's two points
    const int p1 = p0 + TPB;
    float d;

    if (!s_issym) {
        float D0 = sR[0] - sR[9],  D1 = sR[1] - sR[10], D2 = sR[2] - sR[11];
        float D3 = sR[3] - sR[12], D4 = sR[4] - sR[13], D5 = sR[5] - sR[14];
        float D6 = sR[6] - sR[15], D7 = sR[7] - sR[16], D8 = sR[8] - sR[17];
        d = 0.f;
#pragma unroll
        for (int pi = 0; pi < 2; pi++) {
            int p = pi ? p1 : p0;
            float x = mp[3 * p + 0], y = mp[3 * p + 1], z = mp[3 * p + 2];
            float dx = D0 * x + D1 * y + D2 * z;
            float dy = D3 * x + D4 * y + D5 * z;
            float dz = D6 * x + D7 * y + D8 * z;
            d += dx * dx + dy * dy + dz * dz;
        }
    } else {
        // Fill target-rotated points (pair-packed) into shared.
        {
            float T0 = sR[9],  T1 = sR[10], T2 = sR[11];
            float T3 = sR[12], T4 = sR[13], T5 = sR[14];
            float T6 = sR[15], T7 = sR[16], T8 = sR[17];
#pragma unroll
            for (int q = tid; q < NP; q += TPB) {
                float x = mp[3 * q + 0], y = mp[3 * q + 1], z = mp[3 * q + 2];
                float tx = T0 * x + T1 * y + T2 * z;
                float ty = T3 * x + T4 * y + T5 * z;
                float tz = T6 * x + T7 * y + T8 * z;
                int j = q >> 1, h = q & 1;
                sA[4 * j + h] = tx;
                sA[4 * j + 2 + h] = ty;
                sB[4 * j + h] = tz;
                sB[4 * j + 2 + h] = tx * tx + ty * ty + tz * tz;
            }
        }
        float px0, py0, pz0, px1, py1, pz1;
        {
            float P0 = sR[0], P1 = sR[1], P2 = sR[2];
            float P3 = sR[3], P4 = sR[4], P5 = sR[5];
            float P6 = sR[6], P7 = sR[7], P8 = sR[8];
            float x = mp[3 * p0 + 0], y = mp[3 * p0 + 1], z = mp[3 * p0 + 2];
            px0 = P0 * x + P1 * y + P2 * z;
            py0 = P3 * x + P4 * y + P5 * z;
            pz0 = P6 * x + P7 * y + P8 * z;
            x = mp[3 * p1 + 0]; y = mp[3 * p1 + 1]; z = mp[3 * p1 + 2];
            px1 = P0 * x + P1 * y + P2 * z;
            py1 = P3 * x + P4 * y + P5 * z;
            pz1 = P6 * x + P7 * y + P8 * z;
        }
        __syncthreads();

        const unsigned long long ax0 = pack2(-2.f * px0, -2.f * px0);
        const unsigned long long ay0 = pack2(-2.f * py0, -2.f * py0);
        const unsigned long long az0 = pack2(-2.f * pz0, -2.f * pz0);
        const unsigned long long ax1 = pack2(-2.f * px1, -2.f * px1);
        const unsigned long long ay1 = pack2(-2.f * py1, -2.f * py1);
        const unsigned long long az1 = pack2(-2.f * pz1, -2.f * pz1);
        const ulonglong2* __restrict__ pA = (const ulonglong2*)sA;
        const ulonglong2* __restrict__ pB = (const ulonglong2*)sB;

        const float INF = 3.402823466e38f;
        // 4 accumulators per point; each q-pair group i feeds acc[i].
        float m0[4] = {INF, INF, INF, INF};
        float m1[4] = {INF, INF, INF, INF};

        // Software pipeline: current/next register buffers of 4 q-pairs
        // (8 q's) each.  NP/8 = 128 steps.
        ulonglong2 cA[4], cB[4];
#pragma unroll
        for (int i = 0; i < 4; i++) { cA[i] = pA[i]; cB[i] = pB[i]; }

        for (int t = 0; t < NP / 8 - 1; t++) {
            ulonglong2 nA[4], nB[4];
#pragma unroll
            for (int i = 0; i < 4; i++) {       // prefetch next step
                nA[i] = pA[4 * (t + 1) + i];
                nB[i] = pB[4 * (t + 1) + i];
            }
#pragma unroll
            for (int i = 0; i < 4; i++) {       // compute current step
                unsigned long long v;
                float2 vf;
                v = ffma2(ax0, cA[i].x, cB[i].y);
                v = ffma2(ay0, cA[i].y, v);
                v = ffma2(az0, cB[i].x, v);
                vf = unpack2(v);
                m0[i] = fminf(m0[i], fminf(vf.x, vf.y));
                v = ffma2(ax1, cA[i].x, cB[i].y);
                v = ffma2(ay1, cA[i].y, v);
                v = ffma2(az1, cB[i].x, v);
                vf = unpack2(v);
                m1[i] = fminf(m1[i], fminf(vf.x, vf.y));
            }
#pragma unroll
            for (int i = 0; i < 4; i++) { cA[i] = nA[i]; cB[i] = nB[i]; }
        }
        // epilogue: last step
#pragma unroll
        for (int i = 0; i < 4; i++) {
            unsigned long long v;
            float2 vf;
            v = ffma2(ax0, cA[i].x, cB[i].y);
            v = ffma2(ay0, cA[i].y, v);
            v = ffma2(az0, cB[i].x, v);
            vf = unpack2(v);
            m0[i] = fminf(m0[i], fminf(vf.x, vf.y));
            v = ffma2(ax1, cA[i].x, cB[i].y);
            v = ffma2(ay1, cA[i].y, v);
            v = ffma2(az1, cB[i].x, v);
            vf = unpack2(v);
            m1[i] = fminf(m1[i], fminf(vf.x, vf.y));
        }

        float d0 = fminf(fminf(m0[0], m0[1]), fminf(m0[2], m0[3])) +
                   (px0 * px0 + py0 * py0 + pz0 * pz0);
        float d1 = fminf(fminf(m1[0], m1[1]), fminf(m1[2], m1[3])) +
                   (px1 * px1 + py1 * py1 + pz1 * pz1);
        d = d0 + d1;
    }

    // ---- block partial ----
    float tot = block_reduce_128(d, s_red, tid);
    __shared__ int s_last;
    if (tid == 0) {
        g_partials[blockIdx.x] = tot;
        __threadfence();
        unsigned t = atomicAdd(&g_ticket, 1u);
        s_last = (t == GRID - 1) ? 1 : 0;
    }
    __syncthreads();

    // ---- last block: deterministic fixed-order global reduction ----
    if (s_last) {
        __threadfence();   // acquire
        float v = 0.f;
#pragma unroll
        for (int i = 0; i < GRID / TPB; i++)
            v += __ldcg(&g_partials[tid + i * TPB]);
        float total = block_reduce_128(v, s_red, tid);
        if (tid == 0) {
            out[0] = total * (1.0f / (2.0f * NB * NP));
            g_ticket = 0;   // reset for next graph replay
        }
    }
}

extern "C" void kernel_launch(void* const* d_in, const int* in_sizes, int n_in,
                              void* d_out, int out_size) {
    const float* pred = (const float*)d_in[0];
    const float* tgt  = (const float*)d_in[1];
    const float* wt   = (const float*)d_in[2];
    const float* pts  = (const float*)d_in[3];
    const float* sym  = (const float*)d_in[4];
    float* out = (float*)d_out;

    pm_fused_kernel<<<GRID, TPB>>>(pred, tgt, wt, pts, sym, out);
}

// round 8
// speedup vs baseline: 1.1492x; 1.0725x over previous
#include <cuda_runtime.h>

// PMLoss, 2-D tiled. B=128 ROIs, C=22 classes, P=1024 points.
// K1: grid 2048 = 128b x 4 p-chunks x 4 q-chunks, TPB=128, 2 p/thread.
//     Heavy (symmetric) block: partial min over its 256-q tile for 256 p's,
//     written (with |pp|^2 folded) to g_dmin[b][qc][p]. Light: pointwise d
//     written to g_dmin[b][0][p]; qc>0 light blocks exit.
// K2: per-b min-over-qc + sum; ticket last block -> scalar out.

#define NB 128
#define NC 22
#define NP 1024
#define PC 4
#define QC 4
#define PPB (NP / PC)     // 256 p per block
#define QPB (NP / QC)     // 256 q per block
#define TPB 128
#define GRID1 (NB * PC * QC)

__device__ float g_dmin[NB][QC][NP];   // 2 MB scratch
__device__ float g_partials[NB];
__device__ int   g_issym[NB];
__device__ unsigned int g_ticket = 0;

__device__ __forceinline__ void quat2mat(float w, float x, float y, float z,
                                         float* R) {
    R[0] = 1.f - 2.f * (y * y + z * z);
    R[1] = 2.f * (x * y - w * z);
    R[2] = 2.f * (x * z + w * y);
    R[3] = 2.f * (x * y + w * z);
    R[4] = 1.f - 2.f * (x * x + z * z);
    R[5] = 2.f * (y * z - w * x);
    R[6] = 2.f * (x * z - w * y);
    R[7] = 2.f * (y * z + w * x);
    R[8] = 1.f - 2.f * (x * x + y * y);
}

// ---------------- K1: tiled partial-min / pointwise ----------------
__global__ __launch_bounds__(TPB) void pm_tile_kernel(
    const float* __restrict__ pred, const float* __restrict__ tgt,
    const float* __restrict__ wt, const float* __restrict__ pts,
    const float* __restrict__ sym) {
    __shared__ float4 s_pt[QPB];      // target-rotated q tile: (x,y,z,|t|^2)
    __shared__ float sR[18];          // Rp 0..8, Rt 9..17
    __shared__ int s_cls, s_issym;

    const int bid = blockIdx.x;
    const int b = bid >> 4;
    const int pc = (bid >> 2) & 3;
    const int qc = bid & 3;
    const int tid = threadIdx.x;

    // ---- setup: parallel class find (warp 0), quat->mat (lane 0) ----
    if (tid < 32) {
        bool hit = (tid >= 1) && (tid < NC) &&
                   (wt[b * 4 * NC + 4 * tid] > 0.5f);
        unsigned m = __ballot_sync(0xffffffffu, hit);
        if (tid == 0) {
            int cls = m ? (__ffs(m) - 1) : 0;
            s_cls = cls;
            int issym = (sym[cls] > 0.0f) ? 1 : 0;
            s_issym = issym;
            if (pc == 0 && qc == 0) g_issym[b] = issym;
            const float* qp = pred + b * 4 * NC + cls * 4;
            float qw = qp[0], qx = qp[1], qy = qp[2], qz = qp[3];
            float inv = rsqrtf(qw * qw + qx * qx + qy * qy + qz * qz);
            quat2mat(qw * inv, qx * inv, qy * inv, qz * inv, sR);
            const float* qt = tgt + b * 4 * NC + cls * 4;  // unit-norm
            quat2mat(qt[0], qt[1], qt[2], qt[3], sR + 9);
        }
    }
    __syncthreads();

    const int issym = s_issym;
    if (!issym && qc != 0) return;    // light ROI: only qc==0 works

    const int cls = s_cls;
    const float* __restrict__ mp = pts + (size_t)cls * NP * 3;
    const int p0 = pc * PPB + tid;    // this thread's two p's
    const int p1 = p0 + TPB;

    if (!issym) {
        // Pointwise |(Rp-Rt) x|^2 for p0, p1.
        float D0 = sR[0] - sR[9],  D1 = sR[1] - sR[10], D2 = sR[2] - sR[11];
        float D3 = sR[3] - sR[12], D4 = sR[4] - sR[13], D5 = sR[5] - sR[14];
        float D6 = sR[6] - sR[15], D7 = sR[7] - sR[16], D8 = sR[8] - sR[17];
#pragma unroll
        for (int pi = 0; pi < 2; pi++) {
            int p = pi ? p1 : p0;
            float x = mp[3 * p + 0], y = mp[3 * p + 1], z = mp[3 * p + 2];
            float dx = D0 * x + D1 * y + D2 * z;
            float dy = D3 * x + D4 * y + D5 * z;
            float dz = D6 * x + D7 * y + D8 * z;
            g_dmin[b][0][p] = dx * dx + dy * dy + dz * dz;
        }
        return;
    }

    // ---- heavy: fill this block's 256-q target tile ----
    {
        float T0 = sR[9],  T1 = sR[10], T2 = sR[11];
        float T3 = sR[12], T4 = sR[13], T5 = sR[14];
        float T6 = sR[15], T7 = sR[16], T8 = sR[17];
#pragma unroll
        for (int qq = tid; qq < QPB; qq += TPB) {
            int q = qc * QPB + qq;
            float x = mp[3 * q + 0], y = mp[3 * q + 1], z = mp[3 * q + 2];
            float tx = T0 * x + T1 * y + T2 * z;
            float ty = T3 * x + T4 * y + T5 * z;
            float tz = T6 * x + T7 * y + T8 * z;
            s_pt[qq] = make_float4(tx, ty, tz, tx * tx + ty * ty + tz * tz);
        }
    }
    // predicted-rotated p0, p1
    float px0, py0, pz0, px1, py1, pz1;
    {
        float P0 = sR[0], P1 = sR[1], P2 = sR[2];
        float P3 = sR[3], P4 = sR[4], P5 = sR[5];
        float P6 = sR[6], P7 = sR[7], P8 = sR[8];
        float x = mp[3 * p0 + 0], y = mp[3 * p0 + 1], z = mp[3 * p0 + 2];
        px0 = P0 * x + P1 * y + P2 * z;
        py0 = P3 * x + P4 * y + P5 * z;
        pz0 = P6 * x + P7 * y + P8 * z;
        x = mp[3 * p1 + 0]; y = mp[3 * p1 + 1]; z = mp[3 * p1 + 2];
        px1 = P0 * x + P1 * y + P2 * z;
        py1 = P3 * x + P4 * y + P5 * z;
        pz1 = P6 * x + P7 * y + P8 * z;
    }
    __syncthreads();

    const float a0x = -2.f * px0, a0y = -2.f * py0, a0z = -2.f * pz0;
    const float a1x = -2.f * px1, a1y = -2.f * py1, a1z = -2.f * pz1;
    const float INF = 3.402823466e38f;
    float m0a = INF, m0b = INF, m1a = INF, m1b = INF;

#pragma unroll 4
    for (int j = 0; j < QPB / 2; j++) {
        float4 t0 = s_pt[2 * j];
        float4 t1 = s_pt[2 * j + 1];
        float v;
        v = fmaf(a0x, t0.x, t0.w);
        v = fmaf(a0y, t0.y, v);
        v = fmaf(a0z, t0.z, v);
        m0a = fminf(m0a, v);
        v = fmaf(a1x, t0.x, t0.w);
        v = fmaf(a1y, t0.y, v);
        v = fmaf(a1z, t0.z, v);
        m1a = fminf(m1a, v);
        v = fmaf(a0x, t1.x, t1.w);
        v = fmaf(a0y, t1.y, v);
        v = fmaf(a0z, t1.z, v);
        m0b = fminf(m0b, v);
        v = fmaf(a1x, t1.x, t1.w);
        v = fmaf(a1y, t1.y, v);
        v = fmaf(a1z, t1.z, v);
        m1b = fminf(m1b, v);
    }
    g_dmin[b][qc][p0] =
        fminf(m0a, m0b) + (px0 * px0 + py0 * py0 + pz0 * pz0);
    g_dmin[b][qc][p1] =
        fminf(m1a, m1b) + (px1 * px1 + py1 * py1 + pz1 * pz1);
}

// ---------------- K2: combine + reduce ----------------
__global__ __launch_bounds__(256) void pm_reduce_kernel(float* __restrict__ out) {
    __shared__ float s_red[8];
    const int b = blockIdx.x;
    const int tid = threadIdx.x;
    const int issym = g_issym[b];

    float acc = 0.f;
#pragma unroll
    for (int i = 0; i < NP / 256; i++) {
        int p = tid + i * 256;
        float d = g_dmin[b][0][p];
        if (issym) {
            d = fminf(d, g_dmin[b][1][p]);
            d = fminf(d, g_dmin[b][2][p]);
            d = fminf(d, g_dmin[b][3][p]);
        }
        acc += d;
    }
    // block reduce (256 threads)
#pragma unroll
    for (int o = 16; o > 0; o >>= 1)
        acc += __shfl_down_sync(0xffffffffu, acc, o);
    if ((tid & 31) == 0) s_red[tid >> 5] = acc;
    __syncthreads();
    __shared__ int s_last;
    if (tid < 8) {
        acc = s_red[tid];
        acc += __shfl_down_sync(0xffu, acc, 4);
        acc += __shfl_down_sync(0xffu, acc, 2);
        acc += __shfl_down_sync(0xffu, acc, 1);
        if (tid == 0) {
            g_partials[b] = acc;
            __threadfence();
            unsigned t = atomicAdd(&g_ticket, 1u);
            s_last = (t == NB - 1) ? 1 : 0;
        }
    }
    __syncthreads();

    if (s_last) {
        __threadfence();
        float v = (tid < NB) ? __ldcg(&g_partials[tid]) : 0.f;
#pragma unroll
        for (int o = 16; o > 0; o >>= 1)
            v += __shfl_down_sync(0xffffffffu, v, o);
        if ((tid & 31) == 0) s_red[tid >> 5] = v;
        __syncthreads();
        if (tid < 8) {
            v = s_red[tid];
            v += __shfl_down_sync(0xffu, v, 4);
            v += __shfl_down_sync(0xffu, v, 2);
            v += __shfl_down_sync(0xffu, v, 1);
            if (tid == 0) {
                out[0] = v * (1.0f / (2.0f * NB * NP));
                g_ticket = 0;   // reset for next replay
            }
        }
    }
}

extern "C" void kernel_launch(void* const* d_in, const int* in_sizes, int n_in,
                              void* d_out, int out_size) {
    const float* pred = (const float*)d_in[0];
    const float* tgt  = (const float*)d_in[1];
    const float* wt   = (const float*)d_in[2];
    const float* pts  = (const float*)d_in[3];
    const float* sym  = (const float*)d_in[4];
    float* out = (float*)d_out;

    pm_tile_kernel<<<GRID1, TPB>>>(pred, tgt, wt, pts, sym);
    pm_reduce_kernel<<<NB, 256>>>(out);
}